// round 8
// baseline (speedup 1.0000x reference)
#include <cuda_runtime.h>
#include <cuda_fp16.h>
#include <math.h>
#include <stdint.h>

#define BB 32
#define QQ 40
#define LL 1024
#define HH 1024
#define MIN_SIG (1.0f/4096.0f)
#define HALF_LOG_RANGE 4.9999975e-07f
#define MAX_DELTA_C 0.1f

// MLP0 stage (bytes): A 80*40 halves @0, B 32*136 halves @6400; stage 15104B
#define A_OFFb 0
#define B_OFFb 6400
#define STG_B  15104
#define MLP0_SMEM (3 * STG_B)
// Pool stage (bytes): A 80*40 @0, B 32*264 halves @6400; stage 23296B
#define PB_OFFb 6400
#define PSTG_B  23296
#define POOL_SMEM (3 * PSTG_B)

// -------- device scratch --------
__device__ __half g_vid16[BB * LL * HH];
__device__ __half g_w016[2 * HH * HH];
__device__ __half g_W16[BB * 80 * LL];
__device__ __half g_J16[BB * QQ * 2 * HH];
__device__ float g_dp_part[8][BB * QQ * 2];     // [nblk][row*2+out]
__device__ float g_state[BB * QQ * 2];
__device__ float g_txtoff[BB * 2];
__device__ float g_txtctrb[BB * HH];
__device__ float g_ctrb_part[8][BB * HH];

// ---------------- helpers ----------------
__device__ __forceinline__ uint32_t s2u(const void* p) {
    return (uint32_t)__cvta_generic_to_shared(p);
}
__device__ __forceinline__ void ldsm4(uint32_t addr, uint32_t* r) {
    asm volatile("ldmatrix.sync.aligned.m8n8.x4.shared.b16 {%0,%1,%2,%3}, [%4];"
        : "=r"(r[0]), "=r"(r[1]), "=r"(r[2]), "=r"(r[3]) : "r"(addr));
}
__device__ __forceinline__ void ldsm4t(uint32_t addr, uint32_t* r01, uint32_t* r23) {
    asm volatile("ldmatrix.sync.aligned.m8n8.x4.trans.shared.b16 {%0,%1,%2,%3}, [%4];"
        : "=r"(r01[0]), "=r"(r01[1]), "=r"(r23[0]), "=r"(r23[1]) : "r"(addr));
}
__device__ __forceinline__ void cpa16(uint32_t d, const void* g) {
    asm volatile("cp.async.cg.shared.global [%0], [%1], 16;" :: "r"(d), "l"(g));
}
#define CP_COMMIT() asm volatile("cp.async.commit_group;")
#define CP_WAIT(N)  asm volatile("cp.async.wait_group %0;" :: "n"(N))

#define MMA(c, a, b) asm volatile( \
    "mma.sync.aligned.m16n8k16.row.col.f32.f16.f16.f32 " \
    "{%0,%1,%2,%3}, {%4,%5,%6,%7}, {%8,%9}, {%0,%1,%2,%3};\n" \
    : "+f"((c)[0]), "+f"((c)[1]), "+f"((c)[2]), "+f"((c)[3]) \
    : "r"((a)[0]), "r"((a)[1]), "r"((a)[2]), "r"((a)[3]), \
      "r"((b)[0]), "r"((b)[1]))

__device__ __forceinline__ uint32_t packh2(float a, float b) {
    __half2 v; v.x = __float2half(a); v.y = __float2half(b);
    return *(uint32_t*)&v;
}

// ---------------- conversions ----------------
__global__ void k_cvt_vid(const float* __restrict__ src) {
    int i = blockIdx.x * 256 + threadIdx.x;
    float4 v = ((const float4*)src)[i];
    ((uint2*)g_vid16)[i] = make_uint2(packh2(v.x, v.y), packh2(v.z, v.w));
}
__global__ void k_cvt_w0(const float* __restrict__ src) {
    int i = blockIdx.x * 256 + threadIdx.x;
    float4 v = ((const float4*)src)[i];
    ((uint2*)g_w016)[i] = make_uint2(packh2(v.x, v.y), packh2(v.z, v.w));
}

// ---------------- txt offset ----------------
__global__ void k_txt_off(const float* __restrict__ txt_rep,
                          const float* __restrict__ tpw,
                          const float* __restrict__ tpb) {
    int b = blockIdx.x, t = threadIdx.x;
    float a0 = 0.f, a1 = 0.f;
    for (int h = t; h < HH; h += 256) {
        float x = txt_rep[b * HH + h];
        a0 += x * tpw[h * 2 + 0];
        a1 += x * tpw[h * 2 + 1];
    }
    __shared__ float s0[256], s1[256];
    s0[t] = a0; s1[t] = a1; __syncthreads();
    for (int ofs = 128; ofs > 0; ofs >>= 1) {
        if (t < ofs) { s0[t] += s0[t + ofs]; s1[t] += s1[t + ofs]; }
        __syncthreads();
    }
    if (t == 0) {
        g_txtoff[b * 2 + 0] = tanhf(s0[0] + tpb[0]) * HALF_LOG_RANGE;
        g_txtoff[b * 2 + 1] = tanhf(s1[0] + tpb[1]) * HALF_LOG_RANGE;
    }
}

// ---------------- txt contribution: weight-stationary, 128-wide k tiles ----------------
__global__ void k_txt_ctrb(const float* __restrict__ txt_rep,
                           const float* __restrict__ m0w) {
    __shared__ float st[32][128];
    int h0 = blockIdx.x * 128, k0 = blockIdx.y * 128;
    int t = threadIdx.x;
#pragma unroll
    for (int i = 0; i < 16; i++) {
        int idx = t + i * 256;
        int b = idx >> 7, k = idx & 127;
        st[b][k] = txt_rep[b * HH + k0 + k];
    }
    __syncthreads();
    int tx = t & 63;          // h pair
    int ty = t >> 6;          // batch group of 8
    float acc[8][2];
#pragma unroll
    for (int i = 0; i < 8; i++) { acc[i][0] = 0.f; acc[i][1] = 0.f; }
    const float* wbase = m0w + (size_t)(2 * HH + k0) * HH + h0 + tx * 2;
#pragma unroll 4
    for (int k = 0; k < 128; k++) {
        float2 w = *(const float2*)(wbase + (size_t)k * HH);
#pragma unroll
        for (int i = 0; i < 8; i++) {
            float x = st[ty * 8 + i][k];
            acc[i][0] += x * w.x;
            acc[i][1] += x * w.y;
        }
    }
    float* part = g_ctrb_part[blockIdx.y];
#pragma unroll
    for (int i = 0; i < 8; i++) {
        float2 v; v.x = acc[i][0]; v.y = acc[i][1];
        *(float2*)&part[(ty * 8 + i) * HH + h0 + tx * 2] = v;
    }
}

__global__ void k_ctrb_reduce(const float* __restrict__ m0b) {
    int i = blockIdx.x * 256 + threadIdx.x;
    int h = i & (HH - 1);
    float a = m0b[h];
#pragma unroll
    for (int p = 0; p < 8; p++) a += g_ctrb_part[p][i];
    g_txtctrb[i] = a;
}

// ---------------- init ----------------
__global__ void k_init(const float* __restrict__ pred) {
    int r = blockIdx.x * blockDim.x + threadIdx.x;
    if (r < BB * QQ) {
        float c = pred[r * 2 + 0], w = pred[r * 2 + 1];
        g_state[r * 2 + 0] = fminf(fmaxf(c - 0.5f * w, 0.f), 1.f);
        g_state[r * 2 + 1] = fminf(fmaxf(c + 0.5f * w, 0.f), 1.f);
    }
}

// ---------------- gaussian weights -> fp16 ----------------
__global__ void k_weights(const float* __restrict__ vid_mask,
                          const float* __restrict__ ls_p, const float* __restrict__ le_p,
                          const float* __restrict__ sws_p, const float* __restrict__ swe_p) {
    int r = blockIdx.x;
    int b = r / QQ;
    int t = threadIdx.x;
    float s = g_state[r * 2 + 0], e = g_state[r * 2 + 1];
    float width = fmaxf(e - s, 1e-6f);
    float sig_s = fmaxf(expf(ls_p[0] + sws_p[0] * width + g_txtoff[b * 2 + 0]), MIN_SIG);
    float sig_e = fmaxf(expf(le_p[0] + swe_p[0] * width + g_txtoff[b * 2 + 1]), MIN_SIG);
    float inv_ss = 1.0f / sig_s, inv_se = 1.0f / sig_e;

    const float* mrow = vid_mask + (size_t)b * LL;
    float ws[4], we[4];
    float sum_s = 0.f, sum_e = 0.f;
#pragma unroll
    for (int i = 0; i < 4; i++) {
        int l = t + i * 256;
        float tp = (float)l * (1.0f / 1023.0f);
        float m = mrow[l];
        float ds = (tp - s) * inv_ss;
        float vs = expf(-0.5f * ds * ds) * m;
        float de = (tp - e) * inv_se;
        float ve = expf(-0.5f * de * de) * m;
        ws[i] = vs; we[i] = ve;
        sum_s += vs; sum_e += ve;
    }
    __shared__ float r0[256], r1[256];
    r0[t] = sum_s; r1[t] = sum_e; __syncthreads();
    for (int ofs = 128; ofs > 0; ofs >>= 1) {
        if (t < ofs) { r0[t] += r0[t + ofs]; r1[t] += r1[t + ofs]; }
        __syncthreads();
    }
    float is = 1.0f / fmaxf(r0[0], 1e-8f);
    float ie = 1.0f / fmaxf(r1[0], 1e-8f);
    size_t rs = (size_t)(r * 2 + 0) * LL;
    size_t re = (size_t)(r * 2 + 1) * LL;
#pragma unroll
    for (int i = 0; i < 4; i++) {
        int l = t + i * 256;
        g_W16[rs + l] = __float2half(ws[i] * is);
        g_W16[re + l] = __float2half(we[i] * ie);
    }
}

// ---------------- pool GEMM: BN=256, one wave; cp.async 3-stage ----------------
__global__ void __launch_bounds__(256) k_pool_mma() {
    extern __shared__ __half dsm[];
    int b  = blockIdx.y;
    int n0 = blockIdx.x * 256;
    const __half* Ag = g_W16 + (size_t)b * 80 * LL;
    const __half* Bg = g_vid16 + (size_t)b * LL * HH + n0;

    int t = threadIdx.x;
    int lane = t & 31, wid = t >> 5;
    int wn = wid * 32;
    uint32_t sb = s2u(dsm);

    float acc[5][4][4];
#pragma unroll
    for (int i = 0; i < 5; i++)
#pragma unroll
        for (int j = 0; j < 4; j++)
#pragma unroll
            for (int c = 0; c < 4; c++) acc[i][j][c] = 0.f;

#define PPF(K0, STG) do { \
    uint32_t s = sb + (uint32_t)(STG) * PSTG_B; \
    _Pragma("unroll") \
    for (int c = t; c < 320; c += 256) { \
        int m = c >> 2, ch = c & 3; \
        cpa16(s + (uint32_t)((m * 40 + ch * 8) * 2), Ag + (size_t)m * LL + (K0) + ch * 8); \
    } \
    _Pragma("unroll") \
    for (int c = t; c < 1024; c += 256) { \
        int k = c >> 5, ch = c & 31; \
        cpa16(s + PB_OFFb + (uint32_t)((k * 264 + ch * 8) * 2), \
              Bg + (size_t)((K0) + k) * HH + ch * 8); \
    } \
    CP_COMMIT(); } while (0)

#define P_COMPUTE(SBASE) do { \
    _Pragma("unroll") \
    for (int ks = 0; ks < 2; ks++) { \
        uint32_t ah[5][4], bh[4][2]; \
        int ar  = lane & 15; \
        int acf = ks * 16 + ((lane >> 4) << 3); \
        _Pragma("unroll") \
        for (int i = 0; i < 5; i++) \
            ldsm4((SBASE) + (uint32_t)(((i * 16 + ar) * 40 + acf) * 2), ah[i]); \
        int br  = ks * 16 + (lane & 15); \
        int bcf = (lane >> 4) << 3; \
        _Pragma("unroll") \
        for (int jj = 0; jj < 2; jj++) \
            ldsm4t((SBASE) + PB_OFFb + (uint32_t)((br * 264 + wn + jj * 16 + bcf) * 2), \
                   bh[2 * jj], bh[2 * jj + 1]); \
        _Pragma("unroll") \
        for (int i = 0; i < 5; i++) \
            _Pragma("unroll") \
            for (int j = 0; j < 4; j++) \
                MMA(acc[i][j], ah[i], bh[j]); \
    } } while (0)

    PPF(0, 0);
    PPF(32, 1);

    int stg = 0;
    for (int kt = 0; kt < 32; kt++) {
        if (kt + 1 < 32) { CP_WAIT(1); } else { CP_WAIT(0); }
        __syncthreads();
        if (kt + 2 < 32) {
            int ns = stg + 2; if (ns >= 3) ns -= 3;
            PPF((kt + 2) * 32, ns);
        }
        P_COMPUTE(sb + (uint32_t)stg * PSTG_B);
        stg++; if (stg == 3) stg = 0;
    }

    // epilogue -> J fp16
    int g = lane >> 2, tig = lane & 3;
#pragma unroll
    for (int i = 0; i < 5; i++)
#pragma unroll
        for (int j = 0; j < 4; j++) {
            int n = n0 + wn + j * 8 + tig * 2;
#pragma unroll
            for (int half = 0; half < 2; half++) {
                int m = i * 16 + g + half * 8;
                int jr  = b * QQ + (m >> 1);
                int col = (m & 1) * HH + n;
                *(uint32_t*)&g_J16[(size_t)jr * 2048 + col] =
                    packh2(acc[i][j][half * 2 + 0], acc[i][j][half * 2 + 1]);
            }
        }
#undef PPF
#undef P_COMPUTE
}

// ---------------- MLP0 GEMM + fused MLP1 partial dot-products ----------------
__global__ void __launch_bounds__(256) k_mlp0_mma(const float* __restrict__ m1w) {
    extern __shared__ __half dsm[];
    __shared__ float sdp[8][80][2];
    int m0 = blockIdx.y * 80;
    int n0 = blockIdx.x * 128;
    const __half* Ag = g_J16 + (size_t)m0 * 2048;
    const __half* Bg = g_w016 + n0;

    int t = threadIdx.x;
    int lane = t & 31, wid = t >> 5;
    int wn = wid * 16;
    uint32_t sb = s2u(dsm);

    float acc[5][2][4];
#pragma unroll
    for (int i = 0; i < 5; i++)
#pragma unroll
        for (int j = 0; j < 2; j++)
#pragma unroll
            for (int c = 0; c < 4; c++) acc[i][j][c] = 0.f;

#define M_PREFETCH(K0, STG) do { \
    uint32_t s = sb + (uint32_t)(STG) * STG_B; \
    _Pragma("unroll") \
    for (int c = t; c < 320; c += 256) { \
        int m = c >> 2, ch = c & 3; \
        cpa16(s + A_OFFb + (uint32_t)((m * 40 + ch * 8) * 2), \
              Ag + (size_t)m * 2048 + (K0) + ch * 8); \
    } \
    _Pragma("unroll") \
    for (int c = t; c < 512; c += 256) { \
        int k = c >> 4, ch = c & 15; \
        cpa16(s + B_OFFb + (uint32_t)((k * 136 + ch * 8) * 2), \
              Bg + (size_t)((K0) + k) * HH + ch * 8); \
    } \
    CP_COMMIT(); } while (0)

#define M_COMPUTE(SBASE) do { \
    _Pragma("unroll") \
    for (int ks = 0; ks < 2; ks++) { \
        uint32_t ah[5][4], bh[2][2]; \
        int ar  = lane & 15; \
        int acf = ks * 16 + ((lane >> 4) << 3); \
        _Pragma("unroll") \
        for (int i = 0; i < 5; i++) \
            ldsm4((SBASE) + A_OFFb + (uint32_t)(((i * 16 + ar) * 40 + acf) * 2), ah[i]); \
        int br  = ks * 16 + (lane & 15); \
        int bcf = (lane >> 4) << 3; \
        ldsm4t((SBASE) + B_OFFb + (uint32_t)((br * 136 + wn + bcf) * 2), bh[0], bh[1]); \
        _Pragma("unroll") \
        for (int i = 0; i < 5; i++) \
            _Pragma("unroll") \
            for (int j = 0; j < 2; j++) \
                MMA(acc[i][j], ah[i], bh[j]); \
    } } while (0)

    M_PREFETCH(0, 0);
    M_PREFETCH(32, 1);

    int stg = 0;
    for (int kt = 0; kt < 64; kt++) {
        if (kt + 1 < 64) { CP_WAIT(1); } else { CP_WAIT(0); }
        __syncthreads();
        if (kt + 2 < 64) {
            int ns = stg + 2; if (ns >= 3) ns -= 3;
            M_PREFETCH((kt + 2) * 32, ns);
        }
        M_COMPUTE(sb + (uint32_t)stg * STG_B);
        stg++; if (stg == 3) stg = 0;
    }

    // fused epilogue: relu + ctrb, then partial dot with m1w
    int g = lane >> 2, tig = lane & 3;
    float wreg[2][2][2];
#pragma unroll
    for (int j = 0; j < 2; j++) {
        int n = n0 + wn + j * 8 + tig * 2;
        float4 wv = *(const float4*)(m1w + n * 2);
        wreg[j][0][0] = wv.x; wreg[j][0][1] = wv.y;
        wreg[j][1][0] = wv.z; wreg[j][1][1] = wv.w;
    }
#pragma unroll
    for (int i = 0; i < 5; i++)
#pragma unroll
        for (int half = 0; half < 2; half++) {
            int mrow = i * 16 + g + half * 8;
            int row = m0 + mrow;
            int bb = row / QQ;
            float dp0 = 0.f, dp1 = 0.f;
#pragma unroll
            for (int j = 0; j < 2; j++) {
                int n = n0 + wn + j * 8 + tig * 2;
                float v0 = fmaxf(acc[i][j][half * 2 + 0] + g_txtctrb[bb * HH + n], 0.f);
                float v1 = fmaxf(acc[i][j][half * 2 + 1] + g_txtctrb[bb * HH + n + 1], 0.f);
                dp0 += v0 * wreg[j][0][0] + v1 * wreg[j][1][0];
                dp1 += v0 * wreg[j][0][1] + v1 * wreg[j][1][1];
            }
            dp0 += __shfl_xor_sync(0xFFFFFFFFu, dp0, 1);
            dp0 += __shfl_xor_sync(0xFFFFFFFFu, dp0, 2);
            dp1 += __shfl_xor_sync(0xFFFFFFFFu, dp1, 1);
            dp1 += __shfl_xor_sync(0xFFFFFFFFu, dp1, 2);
            if (tig == 0) {
                sdp[wid][mrow][0] = dp0;
                sdp[wid][mrow][1] = dp1;
            }
        }
    __syncthreads();
    if (t < 160) {
        int row = t >> 1, o = t & 1;
        float s = 0.f;
#pragma unroll
        for (int w = 0; w < 8; w++) s += sdp[w][row][o];
        g_dp_part[blockIdx.x][(m0 + row) * 2 + o] = s;
    }
#undef M_PREFETCH
#undef M_COMPUTE
}

// ---------------- final: reduce partials, tanh, state update, output ----------------
__global__ void k_mlp1f(const float* __restrict__ m1b,
                        float* __restrict__ out, int pass, int last) {
    int r = blockIdx.x * 256 + threadIdx.x;
    if (r >= BB * QQ) return;
    float dp0 = m1b[0], dp1 = m1b[1];
#pragma unroll
    for (int nb = 0; nb < 8; nb++) {
        dp0 += g_dp_part[nb][r * 2 + 0];
        dp1 += g_dp_part[nb][r * 2 + 1];
    }
    float d0 = tanhf(dp0) * MAX_DELTA_C;
    float d1 = tanhf(dp1) * MAX_DELTA_C;
    float s = fminf(fmaxf(g_state[r * 2 + 0] + d0, 0.f), 1.f);
    float e = fminf(fmaxf(g_state[r * 2 + 1] + d1, 0.f), 1.f);
    g_state[r * 2 + 0] = s;
    g_state[r * 2 + 1] = e;
    float c = 0.5f * (s + e);
    float w = fmaxf(e - s, 1e-6f);
    int base = (1 + pass) * BB * QQ * 2;
    out[base + r * 2 + 0] = c;
    out[base + r * 2 + 1] = w;
    if (pass == last) {
        out[r * 2 + 0] = c;
        out[r * 2 + 1] = w;
    }
}

extern "C" void kernel_launch(void* const* d_in, const int* in_sizes, int n_in,
                              void* d_out, int out_size) {
    const float* pred = (const float*)d_in[0];
    const float* vid  = (const float*)d_in[1];
    const float* mask = (const float*)d_in[2];
    const float* txt  = (const float*)d_in[3];
    const float* ls   = (const float*)d_in[4];
    const float* le   = (const float*)d_in[5];
    const float* sws  = (const float*)d_in[6];
    const float* swe  = (const float*)d_in[7];
    const float* tpw  = (const float*)d_in[8];
    const float* tpb  = (const float*)d_in[9];
    const float* m0w  = (const float*)d_in[10];
    const float* m0b  = (const float*)d_in[11];
    const float* m1w  = (const float*)d_in[12];
    const float* m1b  = (const float*)d_in[13];
    float* out = (float*)d_out;

    cudaFuncSetAttribute(k_pool_mma, cudaFuncAttributeMaxDynamicSharedMemorySize, POOL_SMEM);
    cudaFuncSetAttribute(k_mlp0_mma, cudaFuncAttributeMaxDynamicSharedMemorySize, MLP0_SMEM);

    k_cvt_vid<<<(BB * LL * HH / 4) / 256, 256>>>(vid);
    k_cvt_w0<<<(2 * HH * HH / 4) / 256, 256>>>(m0w);
    k_txt_off<<<BB, 256>>>(txt, tpw, tpb);
    k_txt_ctrb<<<dim3(HH / 128, 8), 256>>>(txt, m0w);
    k_ctrb_reduce<<<(BB * HH) / 256, 256>>>(m0b);
    k_init<<<(BB * QQ + 255) / 256, 256>>>(pred);

    for (int p = 0; p < 2; p++) {
        k_weights<<<BB * QQ, 256>>>(mask, ls, le, sws, swe);
        k_pool_mma<<<dim3(HH / 256, BB), 256, POOL_SMEM>>>();
        k_mlp0_mma<<<dim3(HH / 128, (BB * QQ) / 80), 256, MLP0_SMEM>>>(m1w);
        k_mlp1f<<<(BB * QQ + 255) / 256, 256>>>(m1b, out, p, 1);
    }
}

// round 9
// speedup vs baseline: 1.0565x; 1.0565x over previous
#include <cuda_runtime.h>
#include <cuda_fp16.h>
#include <math.h>
#include <stdint.h>

#define BB 32
#define QQ 40
#define LL 1024
#define HH 1024
#define MIN_SIG (1.0f/4096.0f)
#define HALF_LOG_RANGE 4.9999975e-07f
#define MAX_DELTA_C 0.1f

// MLP0 stage (bytes): A 80*40 halves @0, B 32*136 halves @6400; stage 15104B
#define A_OFFb 0
#define B_OFFb 6400
#define STG_B  15104
#define MLP0_SMEM (3 * STG_B)
// Pool stage (bytes): A 80*40 @0, B 32*264 halves @6400; stage 23296B
#define PB_OFFb 6400
#define PSTG_B  23296
#define POOL_SMEM (3 * PSTG_B)

// -------- device scratch --------
__device__ __half g_vid16[BB * LL * HH];
__device__ __half g_w016[2 * HH * HH];
__device__ __half g_W16[BB * 80 * LL];
__device__ __half g_J16[BB * QQ * 2 * HH];
__device__ float g_dp_part[8][BB * QQ * 2];     // [nblk][row*2+out]
__device__ float g_state[BB * QQ * 2];
__device__ float g_txtoff[BB * 2];
__device__ float g_txtctrb[BB * HH];
__device__ float g_ctrb_part[16][BB * HH];

// ---------------- helpers ----------------
__device__ __forceinline__ uint32_t s2u(const void* p) {
    return (uint32_t)__cvta_generic_to_shared(p);
}
__device__ __forceinline__ void ldsm4(uint32_t addr, uint32_t* r) {
    asm volatile("ldmatrix.sync.aligned.m8n8.x4.shared.b16 {%0,%1,%2,%3}, [%4];"
        : "=r"(r[0]), "=r"(r[1]), "=r"(r[2]), "=r"(r[3]) : "r"(addr));
}
__device__ __forceinline__ void ldsm4t(uint32_t addr, uint32_t* r01, uint32_t* r23) {
    asm volatile("ldmatrix.sync.aligned.m8n8.x4.trans.shared.b16 {%0,%1,%2,%3}, [%4];"
        : "=r"(r01[0]), "=r"(r01[1]), "=r"(r23[0]), "=r"(r23[1]) : "r"(addr));
}
__device__ __forceinline__ void cpa16(uint32_t d, const void* g) {
    asm volatile("cp.async.cg.shared.global [%0], [%1], 16;" :: "r"(d), "l"(g));
}
#define CP_COMMIT() asm volatile("cp.async.commit_group;")
#define CP_WAIT(N)  asm volatile("cp.async.wait_group %0;" :: "n"(N))

#define MMA(c, a, b) asm volatile( \
    "mma.sync.aligned.m16n8k16.row.col.f32.f16.f16.f32 " \
    "{%0,%1,%2,%3}, {%4,%5,%6,%7}, {%8,%9}, {%0,%1,%2,%3};\n" \
    : "+f"((c)[0]), "+f"((c)[1]), "+f"((c)[2]), "+f"((c)[3]) \
    : "r"((a)[0]), "r"((a)[1]), "r"((a)[2]), "r"((a)[3]), \
      "r"((b)[0]), "r"((b)[1]))

__device__ __forceinline__ uint32_t packh2(float a, float b) {
    __half2 v; v.x = __float2half(a); v.y = __float2half(b);
    return *(uint32_t*)&v;
}

// ---------------- conversions ----------------
__global__ void k_cvt_vid(const float* __restrict__ src) {
    int i = blockIdx.x * 256 + threadIdx.x;
    float4 v = ((const float4*)src)[i];
    ((uint2*)g_vid16)[i] = make_uint2(packh2(v.x, v.y), packh2(v.z, v.w));
}
__global__ void k_cvt_w0(const float* __restrict__ src) {
    int i = blockIdx.x * 256 + threadIdx.x;
    float4 v = ((const float4*)src)[i];
    ((uint2*)g_w016)[i] = make_uint2(packh2(v.x, v.y), packh2(v.z, v.w));
}

// ---------------- txt offset ----------------
__global__ void k_txt_off(const float* __restrict__ txt_rep,
                          const float* __restrict__ tpw,
                          const float* __restrict__ tpb) {
    int b = blockIdx.x, t = threadIdx.x;
    float a0 = 0.f, a1 = 0.f;
    for (int h = t; h < HH; h += 256) {
        float x = txt_rep[b * HH + h];
        a0 += x * tpw[h * 2 + 0];
        a1 += x * tpw[h * 2 + 1];
    }
    __shared__ float s0[256], s1[256];
    s0[t] = a0; s1[t] = a1; __syncthreads();
    for (int ofs = 128; ofs > 0; ofs >>= 1) {
        if (t < ofs) { s0[t] += s0[t + ofs]; s1[t] += s1[t + ofs]; }
        __syncthreads();
    }
    if (t == 0) {
        g_txtoff[b * 2 + 0] = tanhf(s0[0] + tpb[0]) * HALF_LOG_RANGE;
        g_txtoff[b * 2 + 1] = tanhf(s1[0] + tpb[1]) * HALF_LOG_RANGE;
    }
}

// ---------------- txt contribution: weight-stationary (R7 proven config) ----------------
// grid (8 h-tiles, 16 k-tiles); each block serves all 32 batches; weights read once.
__global__ void k_txt_ctrb(const float* __restrict__ txt_rep,
                           const float* __restrict__ m0w) {
    __shared__ float st[32][64];
    int h0 = blockIdx.x * 128, k0 = blockIdx.y * 64;
    int t = threadIdx.x;
#pragma unroll
    for (int i = 0; i < 8; i++) {
        int idx = t + i * 256;
        int b = idx >> 6, k = idx & 63;
        st[b][k] = txt_rep[b * HH + k0 + k];
    }
    __syncthreads();
    int tx = t & 63;          // h pair: h = h0 + tx*2
    int ty = t >> 6;          // batch group of 8
    float acc[8][2];
#pragma unroll
    for (int i = 0; i < 8; i++) { acc[i][0] = 0.f; acc[i][1] = 0.f; }
    const float* wbase = m0w + (size_t)(2 * HH + k0) * HH + h0 + tx * 2;
#pragma unroll 4
    for (int k = 0; k < 64; k++) {
        float2 w = *(const float2*)(wbase + (size_t)k * HH);
#pragma unroll
        for (int i = 0; i < 8; i++) {
            float x = st[ty * 8 + i][k];
            acc[i][0] += x * w.x;
            acc[i][1] += x * w.y;
        }
    }
    float* part = g_ctrb_part[blockIdx.y];
#pragma unroll
    for (int i = 0; i < 8; i++) {
        float2 v; v.x = acc[i][0]; v.y = acc[i][1];
        *(float2*)&part[(ty * 8 + i) * HH + h0 + tx * 2] = v;
    }
}

__global__ void k_ctrb_reduce(const float* __restrict__ m0b) {
    int i = blockIdx.x * 256 + threadIdx.x;
    int h = i & (HH - 1);
    float a = m0b[h];
#pragma unroll
    for (int p = 0; p < 16; p++) a += g_ctrb_part[p][i];
    g_txtctrb[i] = a;
}

// ---------------- init ----------------
__global__ void k_init(const float* __restrict__ pred) {
    int r = blockIdx.x * blockDim.x + threadIdx.x;
    if (r < BB * QQ) {
        float c = pred[r * 2 + 0], w = pred[r * 2 + 1];
        g_state[r * 2 + 0] = fminf(fmaxf(c - 0.5f * w, 0.f), 1.f);
        g_state[r * 2 + 1] = fminf(fmaxf(c + 0.5f * w, 0.f), 1.f);
    }
}

// ---------------- gaussian weights -> fp16 ----------------
__global__ void k_weights(const float* __restrict__ vid_mask,
                          const float* __restrict__ ls_p, const float* __restrict__ le_p,
                          const float* __restrict__ sws_p, const float* __restrict__ swe_p) {
    int r = blockIdx.x;
    int b = r / QQ;
    int t = threadIdx.x;
    float s = g_state[r * 2 + 0], e = g_state[r * 2 + 1];
    float width = fmaxf(e - s, 1e-6f);
    float sig_s = fmaxf(expf(ls_p[0] + sws_p[0] * width + g_txtoff[b * 2 + 0]), MIN_SIG);
    float sig_e = fmaxf(expf(le_p[0] + swe_p[0] * width + g_txtoff[b * 2 + 1]), MIN_SIG);
    float inv_ss = 1.0f / sig_s, inv_se = 1.0f / sig_e;

    const float* mrow = vid_mask + (size_t)b * LL;
    float ws[4], we[4];
    float sum_s = 0.f, sum_e = 0.f;
#pragma unroll
    for (int i = 0; i < 4; i++) {
        int l = t + i * 256;
        float tp = (float)l * (1.0f / 1023.0f);
        float m = mrow[l];
        float ds = (tp - s) * inv_ss;
        float vs = expf(-0.5f * ds * ds) * m;
        float de = (tp - e) * inv_se;
        float ve = expf(-0.5f * de * de) * m;
        ws[i] = vs; we[i] = ve;
        sum_s += vs; sum_e += ve;
    }
    __shared__ float r0[256], r1[256];
    r0[t] = sum_s; r1[t] = sum_e; __syncthreads();
    for (int ofs = 128; ofs > 0; ofs >>= 1) {
        if (t < ofs) { r0[t] += r0[t + ofs]; r1[t] += r1[t + ofs]; }
        __syncthreads();
    }
    float is = 1.0f / fmaxf(r0[0], 1e-8f);
    float ie = 1.0f / fmaxf(r1[0], 1e-8f);
    size_t rs = (size_t)(r * 2 + 0) * LL;
    size_t re = (size_t)(r * 2 + 1) * LL;
#pragma unroll
    for (int i = 0; i < 4; i++) {
        int l = t + i * 256;
        g_W16[rs + l] = __float2half(ws[i] * is);
        g_W16[re + l] = __float2half(we[i] * ie);
    }
}

// ---------------- pool GEMM: BN=256, one wave; cp.async 3-stage ----------------
__global__ void __launch_bounds__(256) k_pool_mma() {
    extern __shared__ __half dsm[];
    int b  = blockIdx.y;
    int n0 = blockIdx.x * 256;
    const __half* Ag = g_W16 + (size_t)b * 80 * LL;
    const __half* Bg = g_vid16 + (size_t)b * LL * HH + n0;

    int t = threadIdx.x;
    int lane = t & 31, wid = t >> 5;
    int wn = wid * 32;
    uint32_t sb = s2u(dsm);

    float acc[5][4][4];
#pragma unroll
    for (int i = 0; i < 5; i++)
#pragma unroll
        for (int j = 0; j < 4; j++)
#pragma unroll
            for (int c = 0; c < 4; c++) acc[i][j][c] = 0.f;

#define PPF(K0, STG) do { \
    uint32_t s = sb + (uint32_t)(STG) * PSTG_B; \
    _Pragma("unroll") \
    for (int c = t; c < 320; c += 256) { \
        int m = c >> 2, ch = c & 3; \
        cpa16(s + (uint32_t)((m * 40 + ch * 8) * 2), Ag + (size_t)m * LL + (K0) + ch * 8); \
    } \
    _Pragma("unroll") \
    for (int c = t; c < 1024; c += 256) { \
        int k = c >> 5, ch = c & 31; \
        cpa16(s + PB_OFFb + (uint32_t)((k * 264 + ch * 8) * 2), \
              Bg + (size_t)((K0) + k) * HH + ch * 8); \
    } \
    CP_COMMIT(); } while (0)

#define P_COMPUTE(SBASE) do { \
    _Pragma("unroll") \
    for (int ks = 0; ks < 2; ks++) { \
        uint32_t ah[5][4], bh[4][2]; \
        int ar  = lane & 15; \
        int acf = ks * 16 + ((lane >> 4) << 3); \
        _Pragma("unroll") \
        for (int i = 0; i < 5; i++) \
            ldsm4((SBASE) + (uint32_t)(((i * 16 + ar) * 40 + acf) * 2), ah[i]); \
        int br  = ks * 16 + (lane & 15); \
        int bcf = (lane >> 4) << 3; \
        _Pragma("unroll") \
        for (int jj = 0; jj < 2; jj++) \
            ldsm4t((SBASE) + PB_OFFb + (uint32_t)((br * 264 + wn + jj * 16 + bcf) * 2), \
                   bh[2 * jj], bh[2 * jj + 1]); \
        _Pragma("unroll") \
        for (int i = 0; i < 5; i++) \
            _Pragma("unroll") \
            for (int j = 0; j < 4; j++) \
                MMA(acc[i][j], ah[i], bh[j]); \
    } } while (0)

    PPF(0, 0);
    PPF(32, 1);

    int stg = 0;
    for (int kt = 0; kt < 32; kt++) {
        if (kt + 1 < 32) { CP_WAIT(1); } else { CP_WAIT(0); }
        __syncthreads();
        if (kt + 2 < 32) {
            int ns = stg + 2; if (ns >= 3) ns -= 3;
            PPF((kt + 2) * 32, ns);
        }
        P_COMPUTE(sb + (uint32_t)stg * PSTG_B);
        stg++; if (stg == 3) stg = 0;
    }

    // epilogue -> J fp16
    int g = lane >> 2, tig = lane & 3;
#pragma unroll
    for (int i = 0; i < 5; i++)
#pragma unroll
        for (int j = 0; j < 4; j++) {
            int n = n0 + wn + j * 8 + tig * 2;
#pragma unroll
            for (int half = 0; half < 2; half++) {
                int m = i * 16 + g + half * 8;
                int jr  = b * QQ + (m >> 1);
                int col = (m & 1) * HH + n;
                *(uint32_t*)&g_J16[(size_t)jr * 2048 + col] =
                    packh2(acc[i][j][half * 2 + 0], acc[i][j][half * 2 + 1]);
            }
        }
#undef PPF
#undef P_COMPUTE
}

// ---------------- MLP0 GEMM + fused MLP1 partial dot-products ----------------
__global__ void __launch_bounds__(256) k_mlp0_mma(const float* __restrict__ m1w) {
    extern __shared__ __half dsm[];
    __shared__ float sdp[8][80][2];
    int m0 = blockIdx.y * 80;
    int n0 = blockIdx.x * 128;
    const __half* Ag = g_J16 + (size_t)m0 * 2048;
    const __half* Bg = g_w016 + n0;

    int t = threadIdx.x;
    int lane = t & 31, wid = t >> 5;
    int wn = wid * 16;
    uint32_t sb = s2u(dsm);

    float acc[5][2][4];
#pragma unroll
    for (int i = 0; i < 5; i++)
#pragma unroll
        for (int j = 0; j < 2; j++)
#pragma unroll
            for (int c = 0; c < 4; c++) acc[i][j][c] = 0.f;

#define M_PREFETCH(K0, STG) do { \
    uint32_t s = sb + (uint32_t)(STG) * STG_B; \
    _Pragma("unroll") \
    for (int c = t; c < 320; c += 256) { \
        int m = c >> 2, ch = c & 3; \
        cpa16(s + A_OFFb + (uint32_t)((m * 40 + ch * 8) * 2), \
              Ag + (size_t)m * 2048 + (K0) + ch * 8); \
    } \
    _Pragma("unroll") \
    for (int c = t; c < 512; c += 256) { \
        int k = c >> 4, ch = c & 15; \
        cpa16(s + B_OFFb + (uint32_t)((k * 136 + ch * 8) * 2), \
              Bg + (size_t)((K0) + k) * HH + ch * 8); \
    } \
    CP_COMMIT(); } while (0)

#define M_COMPUTE(SBASE) do { \
    _Pragma("unroll") \
    for (int ks = 0; ks < 2; ks++) { \
        uint32_t ah[5][4], bh[2][2]; \
        int ar  = lane & 15; \
        int acf = ks * 16 + ((lane >> 4) << 3); \
        _Pragma("unroll") \
        for (int i = 0; i < 5; i++) \
            ldsm4((SBASE) + A_OFFb + (uint32_t)(((i * 16 + ar) * 40 + acf) * 2), ah[i]); \
        int br  = ks * 16 + (lane & 15); \
        int bcf = (lane >> 4) << 3; \
        ldsm4t((SBASE) + B_OFFb + (uint32_t)((br * 136 + wn + bcf) * 2), bh[0], bh[1]); \
        _Pragma("unroll") \
        for (int i = 0; i < 5; i++) \
            _Pragma("unroll") \
            for (int j = 0; j < 2; j++) \
                MMA(acc[i][j], ah[i], bh[j]); \
    } } while (0)

    M_PREFETCH(0, 0);
    M_PREFETCH(32, 1);

    int stg = 0;
    for (int kt = 0; kt < 64; kt++) {
        if (kt + 1 < 64) { CP_WAIT(1); } else { CP_WAIT(0); }
        __syncthreads();
        if (kt + 2 < 64) {
            int ns = stg + 2; if (ns >= 3) ns -= 3;
            M_PREFETCH((kt + 2) * 32, ns);
        }
        M_COMPUTE(sb + (uint32_t)stg * STG_B);
        stg++; if (stg == 3) stg = 0;
    }

    // fused epilogue: relu + ctrb, then partial dot with m1w
    int g = lane >> 2, tig = lane & 3;
    float wreg[2][2][2];
#pragma unroll
    for (int j = 0; j < 2; j++) {
        int n = n0 + wn + j * 8 + tig * 2;
        float4 wv = *(const float4*)(m1w + n * 2);
        wreg[j][0][0] = wv.x; wreg[j][0][1] = wv.y;
        wreg[j][1][0] = wv.z; wreg[j][1][1] = wv.w;
    }
#pragma unroll
    for (int i = 0; i < 5; i++)
#pragma unroll
        for (int half = 0; half < 2; half++) {
            int mrow = i * 16 + g + half * 8;
            int row = m0 + mrow;
            int bb = row / QQ;
            float dp0 = 0.f, dp1 = 0.f;
#pragma unroll
            for (int j = 0; j < 2; j++) {
                int n = n0 + wn + j * 8 + tig * 2;
                float v0 = fmaxf(acc[i][j][half * 2 + 0] + g_txtctrb[bb * HH + n], 0.f);
                float v1 = fmaxf(acc[i][j][half * 2 + 1] + g_txtctrb[bb * HH + n + 1], 0.f);
                dp0 += v0 * wreg[j][0][0] + v1 * wreg[j][1][0];
                dp1 += v0 * wreg[j][0][1] + v1 * wreg[j][1][1];
            }
            dp0 += __shfl_xor_sync(0xFFFFFFFFu, dp0, 1);
            dp0 += __shfl_xor_sync(0xFFFFFFFFu, dp0, 2);
            dp1 += __shfl_xor_sync(0xFFFFFFFFu, dp1, 1);
            dp1 += __shfl_xor_sync(0xFFFFFFFFu, dp1, 2);
            if (tig == 0) {
                sdp[wid][mrow][0] = dp0;
                sdp[wid][mrow][1] = dp1;
            }
        }
    __syncthreads();
    if (t < 160) {
        int row = t >> 1, o = t & 1;
        float s = 0.f;
#pragma unroll
        for (int w = 0; w < 8; w++) s += sdp[w][row][o];
        g_dp_part[blockIdx.x][(m0 + row) * 2 + o] = s;
    }
#undef M_PREFETCH
#undef M_COMPUTE
}

// ---------------- final: reduce partials, tanh, state update, output ----------------
__global__ void k_mlp1f(const float* __restrict__ m1b,
                        float* __restrict__ out, int pass, int last) {
    int r = blockIdx.x * 256 + threadIdx.x;
    if (r >= BB * QQ) return;
    float dp0 = m1b[0], dp1 = m1b[1];
#pragma unroll
    for (int nb = 0; nb < 8; nb++) {
        dp0 += g_dp_part[nb][r * 2 + 0];
        dp1 += g_dp_part[nb][r * 2 + 1];
    }
    float d0 = tanhf(dp0) * MAX_DELTA_C;
    float d1 = tanhf(dp1) * MAX_DELTA_C;
    float s = fminf(fmaxf(g_state[r * 2 + 0] + d0, 0.f), 1.f);
    float e = fminf(fmaxf(g_state[r * 2 + 1] + d1, 0.f), 1.f);
    g_state[r * 2 + 0] = s;
    g_state[r * 2 + 1] = e;
    float c = 0.5f * (s + e);
    float w = fmaxf(e - s, 1e-6f);
    int base = (1 + pass) * BB * QQ * 2;
    out[base + r * 2 + 0] = c;
    out[base + r * 2 + 1] = w;
    if (pass == last) {
        out[r * 2 + 0] = c;
        out[r * 2 + 1] = w;
    }
}

extern "C" void kernel_launch(void* const* d_in, const int* in_sizes, int n_in,
                              void* d_out, int out_size) {
    const float* pred = (const float*)d_in[0];
    const float* vid  = (const float*)d_in[1];
    const float* mask = (const float*)d_in[2];
    const float* txt  = (const float*)d_in[3];
    const float* ls   = (const float*)d_in[4];
    const float* le   = (const float*)d_in[5];
    const float* sws  = (const float*)d_in[6];
    const float* swe  = (const float*)d_in[7];
    const float* tpw  = (const float*)d_in[8];
    const float* tpb  = (const float*)d_in[9];
    const float* m0w  = (const float*)d_in[10];
    const float* m0b  = (const float*)d_in[11];
    const float* m1w  = (const float*)d_in[12];
    const float* m1b  = (const float*)d_in[13];
    float* out = (float*)d_out;

    cudaFuncSetAttribute(k_pool_mma, cudaFuncAttributeMaxDynamicSharedMemorySize, POOL_SMEM);
    cudaFuncSetAttribute(k_mlp0_mma, cudaFuncAttributeMaxDynamicSharedMemorySize, MLP0_SMEM);

    k_cvt_vid<<<(BB * LL * HH / 4) / 256, 256>>>(vid);
    k_cvt_w0<<<(2 * HH * HH / 4) / 256, 256>>>(m0w);
    k_txt_off<<<BB, 256>>>(txt, tpw, tpb);
    k_txt_ctrb<<<dim3(HH / 128, 16), 256>>>(txt, m0w);
    k_ctrb_reduce<<<(BB * HH) / 256, 256>>>(m0b);
    k_init<<<(BB * QQ + 255) / 256, 256>>>(pred);

    for (int p = 0; p < 2; p++) {
        k_weights<<<BB * QQ, 256>>>(mask, ls, le, sws, swe);
        k_pool_mma<<<dim3(HH / 256, BB), 256, POOL_SMEM>>>();
        k_mlp0_mma<<<dim3(HH / 128, (BB * QQ) / 80), 256, MLP0_SMEM>>>(m1w);
        k_mlp1f<<<(BB * QQ + 255) / 256, 256>>>(m1b, out, p, 1);
    }
}

// round 10
// speedup vs baseline: 1.0919x; 1.0335x over previous
#include <cuda_runtime.h>
#include <cuda_fp16.h>
#include <math.h>
#include <stdint.h>

#define BB 32
#define QQ 40
#define LL 1024
#define HH 1024
#define MIN_SIG (1.0f/4096.0f)
#define HALF_LOG_RANGE 4.9999975e-07f
#define MAX_DELTA_C 0.1f

// MLP0 stage (bytes): A 80*40 halves @0, B 32*136 halves @6400; stage 15104B
#define A_OFFb 0
#define B_OFFb 6400
#define STG_B  15104
#define MLP0_SMEM (3 * STG_B)
// Pool stage (bytes): A 80*40 @0, B 32*264 halves @6400; stage 23296B
#define PB_OFFb 6400
#define PSTG_B  23296
#define POOL_SMEM (3 * PSTG_B)

// -------- device scratch --------
__device__ __half g_vid16[BB * LL * HH];
__device__ __half g_w016[3 * HH * HH];          // full 3H rows fp16
__device__ __half g_W16[BB * 80 * LL];
__device__ __half g_J16[BB * QQ * 2 * HH];
__device__ float g_dp_part[8][BB * QQ * 2];
__device__ float g_state[BB * QQ * 2];
__device__ float g_txtoff[BB * 2];
__device__ float g_txtctrb[BB * HH];
__device__ float g_ctrb_part[16][BB * HH];

// ---------------- helpers ----------------
__device__ __forceinline__ uint32_t s2u(const void* p) {
    return (uint32_t)__cvta_generic_to_shared(p);
}
__device__ __forceinline__ void ldsm4(uint32_t addr, uint32_t* r) {
    asm volatile("ldmatrix.sync.aligned.m8n8.x4.shared.b16 {%0,%1,%2,%3}, [%4];"
        : "=r"(r[0]), "=r"(r[1]), "=r"(r[2]), "=r"(r[3]) : "r"(addr));
}
__device__ __forceinline__ void ldsm4t(uint32_t addr, uint32_t* r01, uint32_t* r23) {
    asm volatile("ldmatrix.sync.aligned.m8n8.x4.trans.shared.b16 {%0,%1,%2,%3}, [%4];"
        : "=r"(r01[0]), "=r"(r01[1]), "=r"(r23[0]), "=r"(r23[1]) : "r"(addr));
}
__device__ __forceinline__ void cpa16(uint32_t d, const void* g) {
    asm volatile("cp.async.cg.shared.global [%0], [%1], 16;" :: "r"(d), "l"(g));
}
#define CP_COMMIT() asm volatile("cp.async.commit_group;")
#define CP_WAIT(N)  asm volatile("cp.async.wait_group %0;" :: "n"(N))

#define MMA(c, a, b) asm volatile( \
    "mma.sync.aligned.m16n8k16.row.col.f32.f16.f16.f32 " \
    "{%0,%1,%2,%3}, {%4,%5,%6,%7}, {%8,%9}, {%0,%1,%2,%3};\n" \
    : "+f"((c)[0]), "+f"((c)[1]), "+f"((c)[2]), "+f"((c)[3]) \
    : "r"((a)[0]), "r"((a)[1]), "r"((a)[2]), "r"((a)[3]), \
      "r"((b)[0]), "r"((b)[1]))

__device__ __forceinline__ uint32_t packh2(float a, float b) {
    __half2 v; v.x = __float2half(a); v.y = __float2half(b);
    return *(uint32_t*)&v;
}

// ---------------- conversions ----------------
__global__ void k_cvt_vid(const float* __restrict__ src) {
    int i = blockIdx.x * 256 + threadIdx.x;
    float4 v = ((const float4*)src)[i];
    ((uint2*)g_vid16)[i] = make_uint2(packh2(v.x, v.y), packh2(v.z, v.w));
}
__global__ void k_cvt_w0(const float* __restrict__ src) {
    int i = blockIdx.x * 256 + threadIdx.x;
    float4 v = ((const float4*)src)[i];
    ((uint2*)g_w016)[i] = make_uint2(packh2(v.x, v.y), packh2(v.z, v.w));
}

// ---------------- txt offset ----------------
__global__ void k_txt_off(const float* __restrict__ txt_rep,
                          const float* __restrict__ tpw,
                          const float* __restrict__ tpb) {
    int b = blockIdx.x, t = threadIdx.x;
    float a0 = 0.f, a1 = 0.f;
    for (int h = t; h < HH; h += 256) {
        float x = txt_rep[b * HH + h];
        a0 += x * tpw[h * 2 + 0];
        a1 += x * tpw[h * 2 + 1];
    }
    __shared__ float s0[256], s1[256];
    s0[t] = a0; s1[t] = a1; __syncthreads();
    for (int ofs = 128; ofs > 0; ofs >>= 1) {
        if (t < ofs) { s0[t] += s0[t + ofs]; s1[t] += s1[t + ofs]; }
        __syncthreads();
    }
    if (t == 0) {
        g_txtoff[b * 2 + 0] = tanhf(s0[0] + tpb[0]) * HALF_LOG_RANGE;
        g_txtoff[b * 2 + 1] = tanhf(s1[0] + tpb[1]) * HALF_LOG_RANGE;
    }
}

// ---------------- txt contribution: fp16 weights, 256 blocks ----------------
// grid (16 h-tiles of 64, 16 k-tiles of 64); each block serves all 32 batches.
__global__ void k_txt_ctrb(const float* __restrict__ txt_rep) {
    __shared__ float st[32][64];
    int h0 = blockIdx.x * 64, k0 = blockIdx.y * 64;
    int t = threadIdx.x;
#pragma unroll
    for (int i = 0; i < 8; i++) {
        int idx = t + i * 256;
        int b = idx >> 6, k = idx & 63;
        st[b][k] = txt_rep[b * HH + k0 + k];
    }
    __syncthreads();
    int tx = t & 31;          // h pair: h = h0 + tx*2
    int ty = t >> 5;          // batch group of 4
    float acc[4][2];
#pragma unroll
    for (int i = 0; i < 4; i++) { acc[i][0] = 0.f; acc[i][1] = 0.f; }
    const __half* wbase = g_w016 + (size_t)(2 * HH + k0) * HH + h0 + tx * 2;
#pragma unroll 8
    for (int k = 0; k < 64; k++) {
        float2 w = __half22float2(*(const __half2*)(wbase + (size_t)k * HH));
#pragma unroll
        for (int i = 0; i < 4; i++) {
            float x = st[ty * 4 + i][k];
            acc[i][0] += x * w.x;
            acc[i][1] += x * w.y;
        }
    }
    float* part = g_ctrb_part[blockIdx.y];
#pragma unroll
    for (int i = 0; i < 4; i++) {
        float2 v; v.x = acc[i][0]; v.y = acc[i][1];
        *(float2*)&part[(ty * 4 + i) * HH + h0 + tx * 2] = v;
    }
}

__global__ void k_ctrb_reduce(const float* __restrict__ m0b) {
    int i = blockIdx.x * 256 + threadIdx.x;
    int h = i & (HH - 1);
    float a = m0b[h];
#pragma unroll
    for (int p = 0; p < 16; p++) a += g_ctrb_part[p][i];
    g_txtctrb[i] = a;
}

// ---------------- init ----------------
__global__ void k_init(const float* __restrict__ pred) {
    int r = blockIdx.x * blockDim.x + threadIdx.x;
    if (r < BB * QQ) {
        float c = pred[r * 2 + 0], w = pred[r * 2 + 1];
        g_state[r * 2 + 0] = fminf(fmaxf(c - 0.5f * w, 0.f), 1.f);
        g_state[r * 2 + 1] = fminf(fmaxf(c + 0.5f * w, 0.f), 1.f);
    }
}

// ---------------- gaussian weights -> fp16 (fast exp) ----------------
__global__ void k_weights(const float* __restrict__ vid_mask,
                          const float* __restrict__ ls_p, const float* __restrict__ le_p,
                          const float* __restrict__ sws_p, const float* __restrict__ swe_p) {
    int r = blockIdx.x;
    int b = r / QQ;
    int t = threadIdx.x;
    float s = g_state[r * 2 + 0], e = g_state[r * 2 + 1];
    float width = fmaxf(e - s, 1e-6f);
    float sig_s = fmaxf(__expf(ls_p[0] + sws_p[0] * width + g_txtoff[b * 2 + 0]), MIN_SIG);
    float sig_e = fmaxf(__expf(le_p[0] + swe_p[0] * width + g_txtoff[b * 2 + 1]), MIN_SIG);
    float inv_ss = 1.0f / sig_s, inv_se = 1.0f / sig_e;

    const float* mrow = vid_mask + (size_t)b * LL;
    float ws[4], we[4];
    float sum_s = 0.f, sum_e = 0.f;
#pragma unroll
    for (int i = 0; i < 4; i++) {
        int l = t + i * 256;
        float tp = (float)l * (1.0f / 1023.0f);
        float m = mrow[l];
        float ds = (tp - s) * inv_ss;
        float vs = __expf(-0.5f * ds * ds) * m;
        float de = (tp - e) * inv_se;
        float ve = __expf(-0.5f * de * de) * m;
        ws[i] = vs; we[i] = ve;
        sum_s += vs; sum_e += ve;
    }
    __shared__ float r0[256], r1[256];
    r0[t] = sum_s; r1[t] = sum_e; __syncthreads();
    for (int ofs = 128; ofs > 0; ofs >>= 1) {
        if (t < ofs) { r0[t] += r0[t + ofs]; r1[t] += r1[t + ofs]; }
        __syncthreads();
    }
    float is = 1.0f / fmaxf(r0[0], 1e-8f);
    float ie = 1.0f / fmaxf(r1[0], 1e-8f);
    size_t rs = (size_t)(r * 2 + 0) * LL;
    size_t re = (size_t)(r * 2 + 1) * LL;
#pragma unroll
    for (int i = 0; i < 4; i++) {
        int l = t + i * 256;
        g_W16[rs + l] = __float2half(ws[i] * is);
        g_W16[re + l] = __float2half(we[i] * ie);
    }
}

// ---------------- pool GEMM: BN=256, one wave; cp.async 3-stage ----------------
__global__ void __launch_bounds__(256) k_pool_mma() {
    extern __shared__ __half dsm[];
    int b  = blockIdx.y;
    int n0 = blockIdx.x * 256;
    const __half* Ag = g_W16 + (size_t)b * 80 * LL;
    const __half* Bg = g_vid16 + (size_t)b * LL * HH + n0;

    int t = threadIdx.x;
    int lane = t & 31, wid = t >> 5;
    int wn = wid * 32;
    uint32_t sb = s2u(dsm);

    float acc[5][4][4];
#pragma unroll
    for (int i = 0; i < 5; i++)
#pragma unroll
        for (int j = 0; j < 4; j++)
#pragma unroll
            for (int c = 0; c < 4; c++) acc[i][j][c] = 0.f;

#define PPF(K0, STG) do { \
    uint32_t s = sb + (uint32_t)(STG) * PSTG_B; \
    _Pragma("unroll") \
    for (int c = t; c < 320; c += 256) { \
        int m = c >> 2, ch = c & 3; \
        cpa16(s + (uint32_t)((m * 40 + ch * 8) * 2), Ag + (size_t)m * LL + (K0) + ch * 8); \
    } \
    _Pragma("unroll") \
    for (int c = t; c < 1024; c += 256) { \
        int k = c >> 5, ch = c & 31; \
        cpa16(s + PB_OFFb + (uint32_t)((k * 264 + ch * 8) * 2), \
              Bg + (size_t)((K0) + k) * HH + ch * 8); \
    } \
    CP_COMMIT(); } while (0)

#define P_COMPUTE(SBASE) do { \
    _Pragma("unroll") \
    for (int ks = 0; ks < 2; ks++) { \
        uint32_t ah[5][4], bh[4][2]; \
        int ar  = lane & 15; \
        int acf = ks * 16 + ((lane >> 4) << 3); \
        _Pragma("unroll") \
        for (int i = 0; i < 5; i++) \
            ldsm4((SBASE) + (uint32_t)(((i * 16 + ar) * 40 + acf) * 2), ah[i]); \
        int br  = ks * 16 + (lane & 15); \
        int bcf = (lane >> 4) << 3; \
        _Pragma("unroll") \
        for (int jj = 0; jj < 2; jj++) \
            ldsm4t((SBASE) + PB_OFFb + (uint32_t)((br * 264 + wn + jj * 16 + bcf) * 2), \
                   bh[2 * jj], bh[2 * jj + 1]); \
        _Pragma("unroll") \
        for (int i = 0; i < 5; i++) \
            _Pragma("unroll") \
            for (int j = 0; j < 4; j++) \
                MMA(acc[i][j], ah[i], bh[j]); \
    } } while (0)

    PPF(0, 0);
    PPF(32, 1);

    int stg = 0;
    for (int kt = 0; kt < 32; kt++) {
        if (kt + 1 < 32) { CP_WAIT(1); } else { CP_WAIT(0); }
        __syncthreads();
        if (kt + 2 < 32) {
            int ns = stg + 2; if (ns >= 3) ns -= 3;
            PPF((kt + 2) * 32, ns);
        }
        P_COMPUTE(sb + (uint32_t)stg * PSTG_B);
        stg++; if (stg == 3) stg = 0;
    }

    // epilogue -> J fp16
    int g = lane >> 2, tig = lane & 3;
#pragma unroll
    for (int i = 0; i < 5; i++)
#pragma unroll
        for (int j = 0; j < 4; j++) {
            int n = n0 + wn + j * 8 + tig * 2;
#pragma unroll
            for (int half = 0; half < 2; half++) {
                int m = i * 16 + g + half * 8;
                int jr  = b * QQ + (m >> 1);
                int col = (m & 1) * HH + n;
                *(uint32_t*)&g_J16[(size_t)jr * 2048 + col] =
                    packh2(acc[i][j][half * 2 + 0], acc[i][j][half * 2 + 1]);
            }
        }
#undef PPF
#undef P_COMPUTE
}

// ---------------- MLP0 GEMM + fused MLP1 partial dot-products ----------------
__global__ void __launch_bounds__(256) k_mlp0_mma(const float* __restrict__ m1w) {
    extern __shared__ __half dsm[];
    __shared__ float sdp[8][80][2];
    int m0 = blockIdx.y * 80;
    int n0 = blockIdx.x * 128;
    const __half* Ag = g_J16 + (size_t)m0 * 2048;
    const __half* Bg = g_w016 + n0;

    int t = threadIdx.x;
    int lane = t & 31, wid = t >> 5;
    int wn = wid * 16;
    uint32_t sb = s2u(dsm);

    float acc[5][2][4];
#pragma unroll
    for (int i = 0; i < 5; i++)
#pragma unroll
        for (int j = 0; j < 2; j++)
#pragma unroll
            for (int c = 0; c < 4; c++) acc[i][j][c] = 0.f;

#define M_PREFETCH(K0, STG) do { \
    uint32_t s = sb + (uint32_t)(STG) * STG_B; \
    _Pragma("unroll") \
    for (int c = t; c < 320; c += 256) { \
        int m = c >> 2, ch = c & 3; \
        cpa16(s + A_OFFb + (uint32_t)((m * 40 + ch * 8) * 2), \
              Ag + (size_t)m * 2048 + (K0) + ch * 8); \
    } \
    _Pragma("unroll") \
    for (int c = t; c < 512; c += 256) { \
        int k = c >> 4, ch = c & 15; \
        cpa16(s + B_OFFb + (uint32_t)((k * 136 + ch * 8) * 2), \
              Bg + (size_t)((K0) + k) * HH + ch * 8); \
    } \
    CP_COMMIT(); } while (0)

#define M_COMPUTE(SBASE) do { \
    _Pragma("unroll") \
    for (int ks = 0; ks < 2; ks++) { \
        uint32_t ah[5][4], bh[2][2]; \
        int ar  = lane & 15; \
        int acf = ks * 16 + ((lane >> 4) << 3); \
        _Pragma("unroll") \
        for (int i = 0; i < 5; i++) \
            ldsm4((SBASE) + A_OFFb + (uint32_t)(((i * 16 + ar) * 40 + acf) * 2), ah[i]); \
        int br  = ks * 16 + (lane & 15); \
        int bcf = (lane >> 4) << 3; \
        ldsm4t((SBASE) + B_OFFb + (uint32_t)((br * 136 + wn + bcf) * 2), bh[0], bh[1]); \
        _Pragma("unroll") \
        for (int i = 0; i < 5; i++) \
            _Pragma("unroll") \
            for (int j = 0; j < 2; j++) \
                MMA(acc[i][j], ah[i], bh[j]); \
    } } while (0)

    M_PREFETCH(0, 0);
    M_PREFETCH(32, 1);

    int stg = 0;
    for (int kt = 0; kt < 64; kt++) {
        if (kt + 1 < 64) { CP_WAIT(1); } else { CP_WAIT(0); }
        __syncthreads();
        if (kt + 2 < 64) {
            int ns = stg + 2; if (ns >= 3) ns -= 3;
            M_PREFETCH((kt + 2) * 32, ns);
        }
        M_COMPUTE(sb + (uint32_t)stg * STG_B);
        stg++; if (stg == 3) stg = 0;
    }

    // fused epilogue: relu + ctrb, then partial dot with m1w
    int g = lane >> 2, tig = lane & 3;
    float wreg[2][2][2];
#pragma unroll
    for (int j = 0; j < 2; j++) {
        int n = n0 + wn + j * 8 + tig * 2;
        float4 wv = *(const float4*)(m1w + n * 2);
        wreg[j][0][0] = wv.x; wreg[j][0][1] = wv.y;
        wreg[j][1][0] = wv.z; wreg[j][1][1] = wv.w;
    }
#pragma unroll
    for (int i = 0; i < 5; i++)
#pragma unroll
        for (int half = 0; half < 2; half++) {
            int mrow = i * 16 + g + half * 8;
            int row = m0 + mrow;
            int bb = row / QQ;
            float dp0 = 0.f, dp1 = 0.f;
#pragma unroll
            for (int j = 0; j < 2; j++) {
                int n = n0 + wn + j * 8 + tig * 2;
                float v0 = fmaxf(acc[i][j][half * 2 + 0] + g_txtctrb[bb * HH + n], 0.f);
                float v1 = fmaxf(acc[i][j][half * 2 + 1] + g_txtctrb[bb * HH + n + 1], 0.f);
                dp0 += v0 * wreg[j][0][0] + v1 * wreg[j][1][0];
                dp1 += v0 * wreg[j][0][1] + v1 * wreg[j][1][1];
            }
            dp0 += __shfl_xor_sync(0xFFFFFFFFu, dp0, 1);
            dp0 += __shfl_xor_sync(0xFFFFFFFFu, dp0, 2);
            dp1 += __shfl_xor_sync(0xFFFFFFFFu, dp1, 1);
            dp1 += __shfl_xor_sync(0xFFFFFFFFu, dp1, 2);
            if (tig == 0) {
                sdp[wid][mrow][0] = dp0;
                sdp[wid][mrow][1] = dp1;
            }
        }
    __syncthreads();
    if (t < 160) {
        int row = t >> 1, o = t & 1;
        float s = 0.f;
#pragma unroll
        for (int w = 0; w < 8; w++) s += sdp[w][row][o];
        g_dp_part[blockIdx.x][(m0 + row) * 2 + o] = s;
    }
#undef M_PREFETCH
#undef M_COMPUTE
}

// ---------------- final: reduce partials, tanh, state update, output ----------------
__global__ void k_mlp1f(const float* __restrict__ m1b,
                        float* __restrict__ out, int pass, int last) {
    int r = blockIdx.x * 256 + threadIdx.x;
    if (r >= BB * QQ) return;
    float dp0 = m1b[0], dp1 = m1b[1];
#pragma unroll
    for (int nb = 0; nb < 8; nb++) {
        dp0 += g_dp_part[nb][r * 2 + 0];
        dp1 += g_dp_part[nb][r * 2 + 1];
    }
    float d0 = tanhf(dp0) * MAX_DELTA_C;
    float d1 = tanhf(dp1) * MAX_DELTA_C;
    float s = fminf(fmaxf(g_state[r * 2 + 0] + d0, 0.f), 1.f);
    float e = fminf(fmaxf(g_state[r * 2 + 1] + d1, 0.f), 1.f);
    g_state[r * 2 + 0] = s;
    g_state[r * 2 + 1] = e;
    float c = 0.5f * (s + e);
    float w = fmaxf(e - s, 1e-6f);
    int base = (1 + pass) * BB * QQ * 2;
    out[base + r * 2 + 0] = c;
    out[base + r * 2 + 1] = w;
    if (pass == last) {
        out[r * 2 + 0] = c;
        out[r * 2 + 1] = w;
    }
}

extern "C" void kernel_launch(void* const* d_in, const int* in_sizes, int n_in,
                              void* d_out, int out_size) {
    const float* pred = (const float*)d_in[0];
    const float* vid  = (const float*)d_in[1];
    const float* mask = (const float*)d_in[2];
    const float* txt  = (const float*)d_in[3];
    const float* ls   = (const float*)d_in[4];
    const float* le   = (const float*)d_in[5];
    const float* sws  = (const float*)d_in[6];
    const float* swe  = (const float*)d_in[7];
    const float* tpw  = (const float*)d_in[8];
    const float* tpb  = (const float*)d_in[9];
    const float* m0w  = (const float*)d_in[10];
    const float* m0b  = (const float*)d_in[11];
    const float* m1w  = (const float*)d_in[12];
    const float* m1b  = (const float*)d_in[13];
    float* out = (float*)d_out;

    cudaFuncSetAttribute(k_pool_mma, cudaFuncAttributeMaxDynamicSharedMemorySize, POOL_SMEM);
    cudaFuncSetAttribute(k_mlp0_mma, cudaFuncAttributeMaxDynamicSharedMemorySize, MLP0_SMEM);

    k_cvt_vid<<<(BB * LL * HH / 4) / 256, 256>>>(vid);
    k_cvt_w0<<<(3 * HH * HH / 4) / 256, 256>>>(m0w);
    k_txt_off<<<BB, 256>>>(txt, tpw, tpb);
    k_txt_ctrb<<<dim3(HH / 64, 16), 256>>>(txt);
    k_ctrb_reduce<<<(BB * HH) / 256, 256>>>(m0b);
    k_init<<<(BB * QQ + 255) / 256, 256>>>(pred);

    for (int p = 0; p < 2; p++) {
        k_weights<<<BB * QQ, 256>>>(mask, ls, le, sws, swe);
        k_pool_mma<<<dim3(HH / 256, BB), 256, POOL_SMEM>>>();
        k_mlp0_mma<<<dim3(HH / 128, (BB * QQ) / 80), 256, MLP0_SMEM>>>(m1w);
        k_mlp1f<<<(BB * QQ + 255) / 256, 256>>>(m1b, out, p, 1);
    }
}

// round 11
// speedup vs baseline: 1.1045x; 1.0115x over previous
#include <cuda_runtime.h>
#include <cuda_fp16.h>
#include <math.h>
#include <stdint.h>

#define BB 32
#define QQ 40
#define LL 1024
#define HH 1024
#define MIN_SIG (1.0f/4096.0f)
#define HALF_LOG_RANGE 4.9999975e-07f
#define MAX_DELTA_C 0.1f

#define A_OFFb 0
#define B_OFFb 6400
#define STG_B  15104
#define MLP0_SMEM (3 * STG_B)
#define PB_OFFb 6400
#define PSTG_B  23296
#define POOL_SMEM (3 * PSTG_B)

// -------- device scratch --------
__device__ __half g_vid16[BB * LL * HH];
__device__ __half g_w016[3 * HH * HH];
__device__ __half g_W16[BB * 80 * LL];
__device__ __half g_J16[BB * QQ * 2 * HH];
__device__ float g_dp_part[8][BB * QQ * 2];
__device__ float g_state[BB * QQ * 2];
__device__ float g_txtoff[BB * 2];
__device__ float g_txtctrb[BB * HH];
__device__ float g_ctrb_part[16][BB * HH];

// ---------------- helpers ----------------
__device__ __forceinline__ uint32_t s2u(const void* p) {
    return (uint32_t)__cvta_generic_to_shared(p);
}
__device__ __forceinline__ void ldsm4(uint32_t addr, uint32_t* r) {
    asm volatile("ldmatrix.sync.aligned.m8n8.x4.shared.b16 {%0,%1,%2,%3}, [%4];"
        : "=r"(r[0]), "=r"(r[1]), "=r"(r[2]), "=r"(r[3]) : "r"(addr));
}
__device__ __forceinline__ void ldsm4t(uint32_t addr, uint32_t* r01, uint32_t* r23) {
    asm volatile("ldmatrix.sync.aligned.m8n8.x4.trans.shared.b16 {%0,%1,%2,%3}, [%4];"
        : "=r"(r01[0]), "=r"(r01[1]), "=r"(r23[0]), "=r"(r23[1]) : "r"(addr));
}
__device__ __forceinline__ void cpa16(uint32_t d, const void* g) {
    asm volatile("cp.async.cg.shared.global [%0], [%1], 16;" :: "r"(d), "l"(g));
}
#define CP_COMMIT() asm volatile("cp.async.commit_group;")
#define CP_WAIT(N)  asm volatile("cp.async.wait_group %0;" :: "n"(N))

#define MMA(c, a, b) asm volatile( \
    "mma.sync.aligned.m16n8k16.row.col.f32.f16.f16.f32 " \
    "{%0,%1,%2,%3}, {%4,%5,%6,%7}, {%8,%9}, {%0,%1,%2,%3};\n" \
    : "+f"((c)[0]), "+f"((c)[1]), "+f"((c)[2]), "+f"((c)[3]) \
    : "r"((a)[0]), "r"((a)[1]), "r"((a)[2]), "r"((a)[3]), \
      "r"((b)[0]), "r"((b)[1]))

__device__ __forceinline__ uint32_t packh2(float a, float b) {
    __half2 v; v.x = __float2half(a); v.y = __float2half(b);
    return *(uint32_t*)&v;
}

// ---------------- conversions ----------------
__global__ void k_cvt_vid(const float* __restrict__ src) {
    int i = blockIdx.x * 256 + threadIdx.x;
    float4 v = ((const float4*)src)[i];
    ((uint2*)g_vid16)[i] = make_uint2(packh2(v.x, v.y), packh2(v.z, v.w));
}
__global__ void k_cvt_w0(const float* __restrict__ src) {
    int i = blockIdx.x * 256 + threadIdx.x;
    float4 v = ((const float4*)src)[i];
    ((uint2*)g_w016)[i] = make_uint2(packh2(v.x, v.y), packh2(v.z, v.w));
}

// ---------------- txt offset ----------------
__global__ void k_txt_off(const float* __restrict__ txt_rep,
                          const float* __restrict__ tpw,
                          const float* __restrict__ tpb) {
    int b = blockIdx.x, t = threadIdx.x;
    float a0 = 0.f, a1 = 0.f;
    for (int h = t; h < HH; h += 256) {
        float x = txt_rep[b * HH + h];
        a0 += x * tpw[h * 2 + 0];
        a1 += x * tpw[h * 2 + 1];
    }
    __shared__ float s0[256], s1[256];
    s0[t] = a0; s1[t] = a1; __syncthreads();
    for (int ofs = 128; ofs > 0; ofs >>= 1) {
        if (t < ofs) { s0[t] += s0[t + ofs]; s1[t] += s1[t + ofs]; }
        __syncthreads();
    }
    if (t == 0) {
        g_txtoff[b * 2 + 0] = tanhf(s0[0] + tpb[0]) * HALF_LOG_RANGE;
        g_txtoff[b * 2 + 1] = tanhf(s1[0] + tpb[1]) * HALF_LOG_RANGE;
    }
}

// ---------------- txt contribution: fp16 weights, 256 blocks ----------------
__global__ void k_txt_ctrb(const float* __restrict__ txt_rep) {
    __shared__ float st[32][64];
    int h0 = blockIdx.x * 64, k0 = blockIdx.y * 64;
    int t = threadIdx.x;
#pragma unroll
    for (int i = 0; i < 8; i++) {
        int idx = t + i * 256;
        int b = idx >> 6, k = idx & 63;
        st[b][k] = txt_rep[b * HH + k0 + k];
    }
    __syncthreads();
    int tx = t & 31;
    int ty = t >> 5;
    float acc[4][2];
#pragma unroll
    for (int i = 0; i < 4; i++) { acc[i][0] = 0.f; acc[i][1] = 0.f; }
    const __half* wbase = g_w016 + (size_t)(2 * HH + k0) * HH + h0 + tx * 2;
#pragma unroll 8
    for (int k = 0; k < 64; k++) {
        float2 w = __half22float2(*(const __half2*)(wbase + (size_t)k * HH));
#pragma unroll
        for (int i = 0; i < 4; i++) {
            float x = st[ty * 4 + i][k];
            acc[i][0] += x * w.x;
            acc[i][1] += x * w.y;
        }
    }
    float* part = g_ctrb_part[blockIdx.y];
#pragma unroll
    for (int i = 0; i < 4; i++) {
        float2 v; v.x = acc[i][0]; v.y = acc[i][1];
        *(float2*)&part[(ty * 4 + i) * HH + h0 + tx * 2] = v;
    }
}

__global__ void k_ctrb_reduce(const float* __restrict__ m0b) {
    int i = blockIdx.x * 256 + threadIdx.x;
    int h = i & (HH - 1);
    float a = m0b[h];
#pragma unroll
    for (int p = 0; p < 16; p++) a += g_ctrb_part[p][i];
    g_txtctrb[i] = a;
}

// ---------------- init ----------------
__global__ void k_init(const float* __restrict__ pred) {
    int r = blockIdx.x * blockDim.x + threadIdx.x;
    if (r < BB * QQ) {
        float c = pred[r * 2 + 0], w = pred[r * 2 + 1];
        g_state[r * 2 + 0] = fminf(fmaxf(c - 0.5f * w, 0.f), 1.f);
        g_state[r * 2 + 1] = fminf(fmaxf(c + 0.5f * w, 0.f), 1.f);
    }
}

// ---------------- gaussian weights -> fp16 (fast exp) ----------------
__global__ void k_weights(const float* __restrict__ vid_mask,
                          const float* __restrict__ ls_p, const float* __restrict__ le_p,
                          const float* __restrict__ sws_p, const float* __restrict__ swe_p) {
    int r = blockIdx.x;
    int b = r / QQ;
    int t = threadIdx.x;
    float s = g_state[r * 2 + 0], e = g_state[r * 2 + 1];
    float width = fmaxf(e - s, 1e-6f);
    float sig_s = fmaxf(__expf(ls_p[0] + sws_p[0] * width + g_txtoff[b * 2 + 0]), MIN_SIG);
    float sig_e = fmaxf(__expf(le_p[0] + swe_p[0] * width + g_txtoff[b * 2 + 1]), MIN_SIG);
    float inv_ss = 1.0f / sig_s, inv_se = 1.0f / sig_e;

    const float* mrow = vid_mask + (size_t)b * LL;
    float ws[4], we[4];
    float sum_s = 0.f, sum_e = 0.f;
#pragma unroll
    for (int i = 0; i < 4; i++) {
        int l = t + i * 256;
        float tp = (float)l * (1.0f / 1023.0f);
        float m = mrow[l];
        float ds = (tp - s) * inv_ss;
        float vs = __expf(-0.5f * ds * ds) * m;
        float de = (tp - e) * inv_se;
        float ve = __expf(-0.5f * de * de) * m;
        ws[i] = vs; we[i] = ve;
        sum_s += vs; sum_e += ve;
    }
    __shared__ float r0[256], r1[256];
    r0[t] = sum_s; r1[t] = sum_e; __syncthreads();
    for (int ofs = 128; ofs > 0; ofs >>= 1) {
        if (t < ofs) { r0[t] += r0[t + ofs]; r1[t] += r1[t + ofs]; }
        __syncthreads();
    }
    float is = 1.0f / fmaxf(r0[0], 1e-8f);
    float ie = 1.0f / fmaxf(r1[0], 1e-8f);
    size_t rs = (size_t)(r * 2 + 0) * LL;
    size_t re = (size_t)(r * 2 + 1) * LL;
#pragma unroll
    for (int i = 0; i < 4; i++) {
        int l = t + i * 256;
        g_W16[rs + l] = __float2half(ws[i] * is);
        g_W16[re + l] = __float2half(we[i] * ie);
    }
}

// ---------------- pool GEMM: BN=256, one wave; cp.async 3-stage ----------------
__global__ void __launch_bounds__(256) k_pool_mma() {
    extern __shared__ __half dsm[];
    int b  = blockIdx.y;
    int n0 = blockIdx.x * 256;
    const __half* Ag = g_W16 + (size_t)b * 80 * LL;
    const __half* Bg = g_vid16 + (size_t)b * LL * HH + n0;

    int t = threadIdx.x;
    int lane = t & 31, wid = t >> 5;
    int wn = wid * 32;
    uint32_t sb = s2u(dsm);

    float acc[5][4][4];
#pragma unroll
    for (int i = 0; i < 5; i++)
#pragma unroll
        for (int j = 0; j < 4; j++)
#pragma unroll
            for (int c = 0; c < 4; c++) acc[i][j][c] = 0.f;

#define PPF(K0, STG) do { \
    uint32_t s = sb + (uint32_t)(STG) * PSTG_B; \
    _Pragma("unroll") \
    for (int c = t; c < 320; c += 256) { \
        int m = c >> 2, ch = c & 3; \
        cpa16(s + (uint32_t)((m * 40 + ch * 8) * 2), Ag + (size_t)m * LL + (K0) + ch * 8); \
    } \
    _Pragma("unroll") \
    for (int c = t; c < 1024; c += 256) { \
        int k = c >> 5, ch = c & 31; \
        cpa16(s + PB_OFFb + (uint32_t)((k * 264 + ch * 8) * 2), \
              Bg + (size_t)((K0) + k) * HH + ch * 8); \
    } \
    CP_COMMIT(); } while (0)

#define P_COMPUTE(SBASE) do { \
    _Pragma("unroll") \
    for (int ks = 0; ks < 2; ks++) { \
        uint32_t ah[5][4], bh[4][2]; \
        int ar  = lane & 15; \
        int acf = ks * 16 + ((lane >> 4) << 3); \
        _Pragma("unroll") \
        for (int i = 0; i < 5; i++) \
            ldsm4((SBASE) + (uint32_t)(((i * 16 + ar) * 40 + acf) * 2), ah[i]); \
        int br  = ks * 16 + (lane & 15); \
        int bcf = (lane >> 4) << 3; \
        _Pragma("unroll") \
        for (int jj = 0; jj < 2; jj++) \
            ldsm4t((SBASE) + PB_OFFb + (uint32_t)((br * 264 + wn + jj * 16 + bcf) * 2), \
                   bh[2 * jj], bh[2 * jj + 1]); \
        _Pragma("unroll") \
        for (int i = 0; i < 5; i++) \
            _Pragma("unroll") \
            for (int j = 0; j < 4; j++) \
                MMA(acc[i][j], ah[i], bh[j]); \
    } } while (0)

    PPF(0, 0);
    PPF(32, 1);

    int stg = 0;
    for (int kt = 0; kt < 32; kt++) {
        if (kt + 1 < 32) { CP_WAIT(1); } else { CP_WAIT(0); }
        __syncthreads();
        if (kt + 2 < 32) {
            int ns = stg + 2; if (ns >= 3) ns -= 3;
            PPF((kt + 2) * 32, ns);
        }
        P_COMPUTE(sb + (uint32_t)stg * PSTG_B);
        stg++; if (stg == 3) stg = 0;
    }

    int g = lane >> 2, tig = lane & 3;
#pragma unroll
    for (int i = 0; i < 5; i++)
#pragma unroll
        for (int j = 0; j < 4; j++) {
            int n = n0 + wn + j * 8 + tig * 2;
#pragma unroll
            for (int half = 0; half < 2; half++) {
                int m = i * 16 + g + half * 8;
                int jr  = b * QQ + (m >> 1);
                int col = (m & 1) * HH + n;
                *(uint32_t*)&g_J16[(size_t)jr * 2048 + col] =
                    packh2(acc[i][j][half * 2 + 0], acc[i][j][half * 2 + 1]);
            }
        }
#undef PPF
#undef P_COMPUTE
}

// ---------------- MLP0 GEMM + fused MLP1 partial dot-products ----------------
__global__ void __launch_bounds__(256) k_mlp0_mma(const float* __restrict__ m1w) {
    extern __shared__ __half dsm[];
    __shared__ float sdp[8][80][2];
    int m0 = blockIdx.y * 80;
    int n0 = blockIdx.x * 128;
    const __half* Ag = g_J16 + (size_t)m0 * 2048;
    const __half* Bg = g_w016 + n0;

    int t = threadIdx.x;
    int lane = t & 31, wid = t >> 5;
    int wn = wid * 16;
    uint32_t sb = s2u(dsm);

    float acc[5][2][4];
#pragma unroll
    for (int i = 0; i < 5; i++)
#pragma unroll
        for (int j = 0; j < 2; j++)
#pragma unroll
            for (int c = 0; c < 4; c++) acc[i][j][c] = 0.f;

#define M_PREFETCH(K0, STG) do { \
    uint32_t s = sb + (uint32_t)(STG) * STG_B; \
    _Pragma("unroll") \
    for (int c = t; c < 320; c += 256) { \
        int m = c >> 2, ch = c & 3; \
        cpa16(s + A_OFFb + (uint32_t)((m * 40 + ch * 8) * 2), \
              Ag + (size_t)m * 2048 + (K0) + ch * 8); \
    } \
    _Pragma("unroll") \
    for (int c = t; c < 512; c += 256) { \
        int k = c >> 4, ch = c & 15; \
        cpa16(s + B_OFFb + (uint32_t)((k * 136 + ch * 8) * 2), \
              Bg + (size_t)((K0) + k) * HH + ch * 8); \
    } \
    CP_COMMIT(); } while (0)

#define M_COMPUTE(SBASE) do { \
    _Pragma("unroll") \
    for (int ks = 0; ks < 2; ks++) { \
        uint32_t ah[5][4], bh[2][2]; \
        int ar  = lane & 15; \
        int acf = ks * 16 + ((lane >> 4) << 3); \
        _Pragma("unroll") \
        for (int i = 0; i < 5; i++) \
            ldsm4((SBASE) + A_OFFb + (uint32_t)(((i * 16 + ar) * 40 + acf) * 2), ah[i]); \
        int br  = ks * 16 + (lane & 15); \
        int bcf = (lane >> 4) << 3; \
        ldsm4t((SBASE) + B_OFFb + (uint32_t)((br * 136 + wn + bcf) * 2), bh[0], bh[1]); \
        _Pragma("unroll") \
        for (int i = 0; i < 5; i++) \
            _Pragma("unroll") \
            for (int j = 0; j < 2; j++) \
                MMA(acc[i][j], ah[i], bh[j]); \
    } } while (0)

    M_PREFETCH(0, 0);
    M_PREFETCH(32, 1);

    int stg = 0;
    for (int kt = 0; kt < 64; kt++) {
        if (kt + 1 < 64) { CP_WAIT(1); } else { CP_WAIT(0); }
        __syncthreads();
        if (kt + 2 < 64) {
            int ns = stg + 2; if (ns >= 3) ns -= 3;
            M_PREFETCH((kt + 2) * 32, ns);
        }
        M_COMPUTE(sb + (uint32_t)stg * STG_B);
        stg++; if (stg == 3) stg = 0;
    }

    int g = lane >> 2, tig = lane & 3;
    float wreg[2][2][2];
#pragma unroll
    for (int j = 0; j < 2; j++) {
        int n = n0 + wn + j * 8 + tig * 2;
        float4 wv = *(const float4*)(m1w + n * 2);
        wreg[j][0][0] = wv.x; wreg[j][0][1] = wv.y;
        wreg[j][1][0] = wv.z; wreg[j][1][1] = wv.w;
    }
#pragma unroll
    for (int i = 0; i < 5; i++)
#pragma unroll
        for (int half = 0; half < 2; half++) {
            int mrow = i * 16 + g + half * 8;
            int row = m0 + mrow;
            int bb = row / QQ;
            float dp0 = 0.f, dp1 = 0.f;
#pragma unroll
            for (int j = 0; j < 2; j++) {
                int n = n0 + wn + j * 8 + tig * 2;
                float v0 = fmaxf(acc[i][j][half * 2 + 0] + g_txtctrb[bb * HH + n], 0.f);
                float v1 = fmaxf(acc[i][j][half * 2 + 1] + g_txtctrb[bb * HH + n + 1], 0.f);
                dp0 += v0 * wreg[j][0][0] + v1 * wreg[j][1][0];
                dp1 += v0 * wreg[j][0][1] + v1 * wreg[j][1][1];
            }
            dp0 += __shfl_xor_sync(0xFFFFFFFFu, dp0, 1);
            dp0 += __shfl_xor_sync(0xFFFFFFFFu, dp0, 2);
            dp1 += __shfl_xor_sync(0xFFFFFFFFu, dp1, 1);
            dp1 += __shfl_xor_sync(0xFFFFFFFFu, dp1, 2);
            if (tig == 0) {
                sdp[wid][mrow][0] = dp0;
                sdp[wid][mrow][1] = dp1;
            }
        }
    __syncthreads();
    if (t < 160) {
        int row = t >> 1, o = t & 1;
        float s = 0.f;
#pragma unroll
        for (int w = 0; w < 8; w++) s += sdp[w][row][o];
        g_dp_part[blockIdx.x][(m0 + row) * 2 + o] = s;
    }
#undef M_PREFETCH
#undef M_COMPUTE
}

// ---------------- final: reduce partials, tanh, state update, output ----------------
__global__ void k_mlp1f(const float* __restrict__ m1b,
                        float* __restrict__ out, int pass, int last) {
    int r = blockIdx.x * 256 + threadIdx.x;
    if (r >= BB * QQ) return;
    float dp0 = m1b[0], dp1 = m1b[1];
#pragma unroll
    for (int nb = 0; nb < 8; nb++) {
        dp0 += g_dp_part[nb][r * 2 + 0];
        dp1 += g_dp_part[nb][r * 2 + 1];
    }
    float d0 = tanhf(dp0) * MAX_DELTA_C;
    float d1 = tanhf(dp1) * MAX_DELTA_C;
    float s = fminf(fmaxf(g_state[r * 2 + 0] + d0, 0.f), 1.f);
    float e = fminf(fmaxf(g_state[r * 2 + 1] + d1, 0.f), 1.f);
    g_state[r * 2 + 0] = s;
    g_state[r * 2 + 1] = e;
    float c = 0.5f * (s + e);
    float w = fmaxf(e - s, 1e-6f);
    int base = (1 + pass) * BB * QQ * 2;
    out[base + r * 2 + 0] = c;
    out[base + r * 2 + 1] = w;
    if (pass == last) {
        out[r * 2 + 0] = c;
        out[r * 2 + 1] = w;
    }
}

extern "C" void kernel_launch(void* const* d_in, const int* in_sizes, int n_in,
                              void* d_out, int out_size) {
    const float* pred = (const float*)d_in[0];
    const float* vid  = (const float*)d_in[1];
    const float* mask = (const float*)d_in[2];
    const float* txt  = (const float*)d_in[3];
    const float* ls   = (const float*)d_in[4];
    const float* le   = (const float*)d_in[5];
    const float* sws  = (const float*)d_in[6];
    const float* swe  = (const float*)d_in[7];
    const float* tpw  = (const float*)d_in[8];
    const float* tpb  = (const float*)d_in[9];
    const float* m0w  = (const float*)d_in[10];
    const float* m0b  = (const float*)d_in[11];
    const float* m1w  = (const float*)d_in[12];
    const float* m1b  = (const float*)d_in[13];
    float* out = (float*)d_out;

    static cudaStream_t s1 = nullptr;
    static cudaEvent_t ev_fork = nullptr, ev_join = nullptr;
    if (s1 == nullptr) {
        cudaStreamCreateWithFlags(&s1, cudaStreamNonBlocking);
        cudaEventCreateWithFlags(&ev_fork, cudaEventDisableTiming);
        cudaEventCreateWithFlags(&ev_join, cudaEventDisableTiming);
        cudaFuncSetAttribute(k_pool_mma, cudaFuncAttributeMaxDynamicSharedMemorySize, POOL_SMEM);
        cudaFuncSetAttribute(k_mlp0_mma, cudaFuncAttributeMaxDynamicSharedMemorySize, MLP0_SMEM);
    }

    // main: w0 conversion first (side chain depends on it)
    k_cvt_w0<<<(3 * HH * HH / 4) / 256, 256>>>(m0w);
    cudaEventRecord(ev_fork, 0);

    // side stream: txt chain (latency-bound) overlapped with vid conversion (BW-bound)
    cudaStreamWaitEvent(s1, ev_fork, 0);
    k_txt_off<<<BB, 256, 0, s1>>>(txt, tpw, tpb);
    k_txt_ctrb<<<dim3(HH / 64, 16), 256, 0, s1>>>(txt);
    k_ctrb_reduce<<<(BB * HH) / 256, 256, 0, s1>>>(m0b);
    cudaEventRecord(ev_join, s1);

    // main: vid conversion + init concurrently
    k_cvt_vid<<<(BB * LL * HH / 4) / 256, 256>>>(vid);
    k_init<<<(BB * QQ + 255) / 256, 256>>>(pred);
    cudaStreamWaitEvent(0, ev_join, 0);

    for (int p = 0; p < 2; p++) {
        k_weights<<<BB * QQ, 256>>>(mask, ls, le, sws, swe);
        k_pool_mma<<<dim3(HH / 256, BB), 256, POOL_SMEM>>>();
        k_mlp0_mma<<<dim3(HH / 128, (BB * QQ) / 80), 256, MLP0_SMEM>>>(m1w);
        k_mlp1f<<<(BB * QQ + 255) / 256, 256>>>(m1b, out, p, 1);
    }
}